// round 13
// baseline (speedup 1.0000x reference)
#include <cuda_runtime.h>

// Sampler_8658654069314: temperature sampling, B=256 rows, V=128000 vocab.
// Greedy rows (t==0): argmax(logits). Sampled rows: Gumbel-max over logits/t
// with JAX threefry2x32 partitionable-mode PRNG, key (0, 42), fold out0^out1.
// OUTPUT IS WRITTEN AS float32 (token values are exactly representable).

#define NB   256
#define NV   128000
#define SEG  25
#define COLS (NV / SEG)            // 5120
#define TPB  256
#define NITER (COLS / (TPB * 4))   // 5 float4 iterations per thread

// Deterministic partial-argmax scratch (no device allocation allowed).
__device__ float g_pval[NB * SEG];
__device__ int   g_pidx[NB * SEG];

// threefry2x32, key = (0, 42), counter = (hi=0, lo=ctr), 20 rounds.
// Partitionable-mode 32-bit draw = out0 ^ out1.
__device__ __forceinline__ unsigned threefry_fold(unsigned ctr) {
    const unsigned ks0 = 0u;
    const unsigned ks1 = 42u;
    const unsigned ks2 = 0x1BD11BDAu ^ ks0 ^ ks1;   // 0x1BD11BF0
    unsigned x0 = ks0;            // 0 + ks0
    unsigned x1 = ctr + ks1;      // ctr + ks1
#define TF_R(r) { x0 += x1; x1 = __funnelshift_l(x1, x1, (r)); x1 ^= x0; }
    TF_R(13) TF_R(15) TF_R(26) TF_R(6)
    x0 += ks1; x1 += ks2 + 1u;
    TF_R(17) TF_R(29) TF_R(16) TF_R(24)
    x0 += ks2; x1 += ks0 + 2u;
    TF_R(13) TF_R(15) TF_R(26) TF_R(6)
    x0 += ks0; x1 += ks1 + 3u;
    TF_R(17) TF_R(29) TF_R(16) TF_R(24)
    x0 += ks1; x1 += ks2 + 4u;
    TF_R(13) TF_R(15) TF_R(26) TF_R(6)
    x0 += ks2; x1 += ks0 + 5u;
#undef TF_R
    return x0 ^ x1;
}

// Accurate log(u) for u in [2^-126, 1). Cephes-style: relative-accurate near
// u->1 (critical: -log(u) can be ~1e-7 for the Gumbel winner). Branch-free,
// independent of --use_fast_math.
__device__ __forceinline__ float log_accurate(float u) {
    int   ib = __float_as_int(u);
    int   e  = (ib >> 23) - 126;                              // u = m * 2^e, m in [0.5,1)
    float m  = __int_as_float((ib & 0x007FFFFF) | 0x3F000000);
    bool  sm = m < 0.70710678f;
    float x  = sm ? fmaf(2.0f, m, -1.0f) : (m - 1.0f);        // exact in both branches
    e -= (int)sm;

    float z = x * x;
    float p =              7.0376836292e-2f;
    p = fmaf(p, x, -1.1514610310e-1f);
    p = fmaf(p, x,  1.1676998740e-1f);
    p = fmaf(p, x, -1.2420140846e-1f);
    p = fmaf(p, x,  1.4249322787e-1f);
    p = fmaf(p, x, -1.6668057665e-1f);
    p = fmaf(p, x,  2.0000714765e-1f);
    p = fmaf(p, x, -2.4999993993e-1f);
    p = fmaf(p, x,  3.3333331174e-1f);
    float fe = (float)e;
    float y  = x * z * p;                     // x^3 * P(x)
    y = fmaf(fe, -2.12194440e-4f, y);         // + e * ln2_lo
    y = fmaf(-0.5f, z, y);                    // - x^2/2
    float r = x + y;
    r = fmaf(fe, 0.693359375f, r);            // + e * ln2_hi (exact product)
    return r;
}

__device__ __forceinline__ float gumbel32(unsigned bits) {
    // JAX uniform: u0 = bitcast(bits>>9 | 0x3f800000) - 1; u = max(u0, tiny)
    float u0 = __uint_as_float((bits >> 9) | 0x3F800000u) - 1.0f;
    float u  = fmaxf(u0, 1.17549435e-38f);
    float w  = -log_accurate(u);              // w in (1.19e-7, 87.34] -> relative-accurate
    return -__logf(w);                        // outer log: 4e-6 abs err, harmless vs Exp(1) gaps
}

__global__ void __launch_bounds__(TPB)
sampler_main(const float* __restrict__ logits, const float* __restrict__ temps) {
    const int row = blockIdx.y;
    const int seg = blockIdx.x;
    const int tid = threadIdx.x;
    const float t = temps[row];
    const float* p = logits + (size_t)row * NV + (size_t)seg * COLS;

    float best = __int_as_float(0xff800000);  // -inf
    int   bidx = NV;

    if (t == 0.0f) {
        // Greedy: argmax of raw logits (first occurrence wins).
#pragma unroll 1
        for (int it = 0; it < NITER; ++it) {
            int c = (it * TPB + tid) * 4;
            float4 x = *reinterpret_cast<const float4*>(p + c);
            float v[4] = {x.x, x.y, x.z, x.w};
#pragma unroll
            for (int k = 0; k < 4; ++k) {
                if (v[k] > best) { best = v[k]; bidx = seg * COLS + c + k; }
            }
        }
    } else {
        const float invT = 1.0f / t;
        const unsigned ibase = (unsigned)row * (unsigned)NV + (unsigned)(seg * COLS);
#pragma unroll 1
        for (int it = 0; it < NITER; ++it) {
            int c = (it * TPB + tid) * 4;
            float4 x = *reinterpret_cast<const float4*>(p + c);
            unsigned bits[4];
#pragma unroll
            for (int k = 0; k < 4; ++k) bits[k] = threefry_fold(ibase + (unsigned)(c + k));
            float xv[4] = {x.x, x.y, x.z, x.w};
#pragma unroll
            for (int k = 0; k < 4; ++k) {
                float g = gumbel32(bits[k]);
                float v = fmaf(xv[k], invT, g);
                if (v > best) { best = v; bidx = seg * COLS + c + k; }
            }
        }
    }

    // Block-level argmax reduction (tie-break: smaller index).
    __shared__ float sv[TPB];
    __shared__ int   si[TPB];
    sv[tid] = best; si[tid] = bidx;
    __syncthreads();
#pragma unroll
    for (int s = TPB / 2; s > 0; s >>= 1) {
        if (tid < s) {
            float v2 = sv[tid + s]; int i2 = si[tid + s];
            float v1 = sv[tid];     int i1 = si[tid];
            if (v2 > v1 || (v2 == v1 && i2 < i1)) { sv[tid] = v2; si[tid] = i2; }
        }
        __syncthreads();
    }
    if (tid == 0) {
        g_pval[row * SEG + seg] = sv[0];
        g_pidx[row * SEG + seg] = si[0];
    }
}

__global__ void sampler_reduce(float* __restrict__ out) {
    const int r = threadIdx.x;                // 256 threads, one per row
    float best = __int_as_float(0xff800000);
    int   bi   = NV;
#pragma unroll 1
    for (int s = 0; s < SEG; ++s) {
        float v = g_pval[r * SEG + s];
        int   i = g_pidx[r * SEG + s];
        if (v > best || (v == best && i < bi)) { best = v; bi = i; }
    }
    out[r] = (float)bi;   // output dtype is float32: tokens < 2^24 are exact
}

extern "C" void kernel_launch(void* const* d_in, const int* in_sizes, int n_in,
                              void* d_out, int out_size) {
    const float* logits = (const float*)d_in[0];   // [256, 128000] f32
    const float* temps  = (const float*)d_in[1];   // [256] f32
    (void)in_sizes; (void)n_in; (void)out_size;

    dim3 grid(SEG, NB);
    sampler_main<<<grid, TPB>>>(logits, temps);
    sampler_reduce<<<1, NB>>>((float*)d_out);
}

// round 14
// speedup vs baseline: 1.0365x; 1.0365x over previous
#include <cuda_runtime.h>

// Sampler_8658654069314: temperature sampling, B=256 rows, V=128000 vocab.
// Greedy rows (t==0): argmax(logits). Sampled rows: Gumbel-max over logits/t
// with JAX threefry2x32 partitionable-mode PRNG, key (0, 42), fold out0^out1.
// Output dtype is float32 (token values < 2^24, exactly representable).
//
// R14: pipe-balance the threefry rotate. rotl(x,r) = lo|hi of x*2^r via one
// IMAD.WIDE on the FMA pipe + a single fused (lo|hi)^x0 LOP3 on the ALU pipe,
// instead of SHF+LOP3 both on the ALU pipe (which was the measured roofline).
// Also: warp-per-row shuffle reduce instead of the serial-LDG-chain reduce.

#define NB   256
#define NV   128000
#define SEG  25
#define COLS (NV / SEG)            // 5120
#define TPB  256
#define NITER (COLS / (TPB * 4))   // 5 float4 iterations per thread

// Deterministic partial-argmax scratch (no device allocation allowed).
__device__ float g_pval[NB * SEG];
__device__ int   g_pidx[NB * SEG];

// threefry2x32, key = (0, 42), counter = (hi=0, lo=ctr), 20 rounds.
// Partitionable-mode 32-bit draw = out0 ^ out1.
// Rotate via 32x32->64 multiply: lo32(x*2^r) = x<<r, hi32(x*2^r) = x>>(32-r).
// IMAD.WIDE lands on the fma pipe; (lo|hi)^x0 is one LOP3 on the alu pipe.
__device__ __forceinline__ unsigned threefry_fold(unsigned ctr) {
    const unsigned ks0 = 0u;
    const unsigned ks1 = 42u;
    const unsigned ks2 = 0x1BD11BDAu ^ ks0 ^ ks1;   // 0x1BD11BF0
    unsigned x0 = ks0;            // 0 + ks0
    unsigned x1 = ctr + ks1;      // ctr + ks1
#define TF_R(r) {                                                        \
        x0 += x1;                                                        \
        unsigned long long w_ = (unsigned long long)x1 * (1u << (r));    \
        x1 = ((unsigned)w_ | (unsigned)(w_ >> 32)) ^ x0;                 \
    }
    TF_R(13) TF_R(15) TF_R(26) TF_R(6)
    x0 += ks1; x1 += ks2 + 1u;
    TF_R(17) TF_R(29) TF_R(16) TF_R(24)
    x0 += ks2; x1 += ks0 + 2u;
    TF_R(13) TF_R(15) TF_R(26) TF_R(6)
    x0 += ks0; x1 += ks1 + 3u;
    TF_R(17) TF_R(29) TF_R(16) TF_R(24)
    x0 += ks1; x1 += ks2 + 4u;
    TF_R(13) TF_R(15) TF_R(26) TF_R(6)
    x0 += ks2; x1 += ks0 + 5u;
#undef TF_R
    return x0 ^ x1;
}

// Accurate log(u) for u in [2^-126, 1). Cephes-style: relative-accurate near
// u->1 (critical: -log(u) can be ~1e-7 for the Gumbel winner). Branch-free,
// independent of --use_fast_math. Mostly FFMA (fma pipe).
__device__ __forceinline__ float log_accurate(float u) {
    int   ib = __float_as_int(u);
    int   e  = (ib >> 23) - 126;                              // u = m * 2^e, m in [0.5,1)
    float m  = __int_as_float((ib & 0x007FFFFF) | 0x3F000000);
    bool  sm = m < 0.70710678f;
    float x  = sm ? fmaf(2.0f, m, -1.0f) : (m - 1.0f);        // exact in both branches
    e -= (int)sm;

    float z = x * x;
    float p =              7.0376836292e-2f;
    p = fmaf(p, x, -1.1514610310e-1f);
    p = fmaf(p, x,  1.1676998740e-1f);
    p = fmaf(p, x, -1.2420140846e-1f);
    p = fmaf(p, x,  1.4249322787e-1f);
    p = fmaf(p, x, -1.6668057665e-1f);
    p = fmaf(p, x,  2.0000714765e-1f);
    p = fmaf(p, x, -2.4999993993e-1f);
    p = fmaf(p, x,  3.3333331174e-1f);
    float fe = (float)e;
    float y  = x * z * p;                     // x^3 * P(x)
    y = fmaf(fe, -2.12194440e-4f, y);         // + e * ln2_lo
    y = fmaf(-0.5f, z, y);                    // - x^2/2
    float r = x + y;
    r = fmaf(fe, 0.693359375f, r);            // + e * ln2_hi (exact product)
    return r;
}

__device__ __forceinline__ float gumbel32(unsigned bits) {
    // JAX uniform: u0 = bitcast(bits>>9 | 0x3f800000) - 1; u = max(u0, tiny)
    float u0 = __uint_as_float((bits >> 9) | 0x3F800000u) - 1.0f;
    float u  = fmaxf(u0, 1.17549435e-38f);
    float w  = -log_accurate(u);              // relative-accurate where it matters
    return -__logf(w);                        // MUFU.LG2 path: 4e-6 abs err, harmless
}

__global__ void __launch_bounds__(TPB)
sampler_main(const float* __restrict__ logits, const float* __restrict__ temps) {
    const int row = blockIdx.y;
    const int seg = blockIdx.x;
    const int tid = threadIdx.x;
    const float t = temps[row];
    const float* p = logits + (size_t)row * NV + (size_t)seg * COLS;

    float best = __int_as_float(0xff800000);  // -inf
    int   bidx = NV;

    if (t == 0.0f) {
        // Greedy: argmax of raw logits (first occurrence wins).
#pragma unroll 1
        for (int it = 0; it < NITER; ++it) {
            int c = (it * TPB + tid) * 4;
            float4 x = *reinterpret_cast<const float4*>(p + c);
            float v[4] = {x.x, x.y, x.z, x.w};
#pragma unroll
            for (int k = 0; k < 4; ++k) {
                if (v[k] > best) { best = v[k]; bidx = seg * COLS + c + k; }
            }
        }
    } else {
        const float invT = 1.0f / t;
        const unsigned ibase = (unsigned)row * (unsigned)NV + (unsigned)(seg * COLS);
#pragma unroll 1
        for (int it = 0; it < NITER; ++it) {
            int c = (it * TPB + tid) * 4;
            float4 x = *reinterpret_cast<const float4*>(p + c);
            unsigned bits[4];
#pragma unroll
            for (int k = 0; k < 4; ++k) bits[k] = threefry_fold(ibase + (unsigned)(c + k));
            float xv[4] = {x.x, x.y, x.z, x.w};
#pragma unroll
            for (int k = 0; k < 4; ++k) {
                float g = gumbel32(bits[k]);
                float v = fmaf(xv[k], invT, g);
                if (v > best) { best = v; bidx = seg * COLS + c + k; }
            }
        }
    }

    // Block-level argmax reduction (tie-break: smaller index).
    __shared__ float sv[TPB];
    __shared__ int   si[TPB];
    sv[tid] = best; si[tid] = bidx;
    __syncthreads();
#pragma unroll
    for (int s = TPB / 2; s > 0; s >>= 1) {
        if (tid < s) {
            float v2 = sv[tid + s]; int i2 = si[tid + s];
            float v1 = sv[tid];     int i1 = si[tid];
            if (v2 > v1 || (v2 == v1 && i2 < i1)) { sv[tid] = v2; si[tid] = i2; }
        }
        __syncthreads();
    }
    if (tid == 0) {
        g_pval[row * SEG + seg] = sv[0];
        g_pidx[row * SEG + seg] = si[0];
    }
}

// Warp-per-row reduce: lane s holds segment s (s < SEG), 5-step shuffle argmax.
// Ties resolve to the smaller index. 32 blocks x (32,8) threads cover 256 rows.
__global__ void __launch_bounds__(256)
sampler_reduce(float* __restrict__ out) {
    const int row  = blockIdx.x * 8 + threadIdx.y;
    const int lane = threadIdx.x;

    float v = __int_as_float(0xff800000);
    int   i = NV;
    if (lane < SEG) {
        v = g_pval[row * SEG + lane];
        i = g_pidx[row * SEG + lane];
    }
#pragma unroll
    for (int s = 16; s > 0; s >>= 1) {
        float v2 = __shfl_down_sync(0xFFFFFFFFu, v, s);
        int   i2 = __shfl_down_sync(0xFFFFFFFFu, i, s);
        if (v2 > v || (v2 == v && i2 < i)) { v = v2; i = i2; }
    }
    if (lane == 0) out[row] = (float)i;   // float32 output: tokens < 2^24 exact
}

extern "C" void kernel_launch(void* const* d_in, const int* in_sizes, int n_in,
                              void* d_out, int out_size) {
    const float* logits = (const float*)d_in[0];   // [256, 128000] f32
    const float* temps  = (const float*)d_in[1];   // [256] f32
    (void)in_sizes; (void)n_in; (void)out_size;

    dim3 grid(SEG, NB);
    sampler_main<<<grid, TPB>>>(logits, temps);
    sampler_reduce<<<32, dim3(32, 8)>>>((float*)d_out);
}